// round 12
// baseline (speedup 1.0000x reference)
#include <cuda_runtime.h>
#include <cuda_bf16.h>
#include <cstdint>

#define BQ    2048
#define DIM   1024
#define NROW  4096
#define XPAD  4352
#define GTILES 304
#define TINV  14.285714285714285f
#define LOG2E 1.4426950408889634f
#define LN2F  0.6931471805599453f
#define C1EXP (TINV * LOG2E)
#define BCAP  64

// ---------------- scratch (device globals; zero-initialized, self-cleaning) ----------------
__device__ __nv_bfloat16 g_X[(size_t)XPAD * DIM];
__device__ int   g_lab[NROW];
__device__ float g_acc[7][NROW];      // [0]=E  [1..6]=P0,P1,Pe,Pex,Pe2,Pe2x
__device__ float g_loss2;             // samix sum
__device__ int   g_cnt[1000];
__device__ int   g_bucket[1000 * BCAP];
__device__ unsigned char g_tmask[1000];

__device__ __forceinline__ float ex2f(float y)
{
    float r;
    asm("ex2.approx.ftz.f32 %0, %1;" : "=f"(r) : "f"(y));
    return r;
}
__device__ __forceinline__ float lg2f(float y)
{
    float r;
    asm("lg2.approx.ftz.f32 %0, %1;" : "=f"(r) : "f"(y));
    return r;
}

// ---------------- prep: X(bf16, padded) + rep_labels + buckets + target mask ----------------
__global__ void prep_all(const float* __restrict__ feats,
                         const float* __restrict__ points,
                         const int* __restrict__ labels,
                         const int* __restrict__ tlab, int ntl,
                         const int* __restrict__ prevp)
{
    const int PREV = prevp ? *prevp : 100;
    int idx = blockIdx.x * blockDim.x + threadIdx.x;

    if (idx < NROW) g_lab[idx] = labels[idx & (BQ - 1)];
    if (idx < BQ) {
        int lab = labels[idx];
        int p = atomicAdd(&g_cnt[lab], 1);
        if (p < BCAP) g_bucket[lab * BCAP + p] = idx;
    }
    if (idx < ntl) g_tmask[tlab[idx]] = 1;

    int r = idx >> 8;
    int c = (idx & 255) << 2;
    if (r >= XPAD) return;
    float4 v = make_float4(0.f, 0.f, 0.f, 0.f);
    if (r < NROW) {
        const float* src = feats + ((r < BQ) ? (size_t)r * (2 * DIM)
                                             : (size_t)(r - BQ) * (2 * DIM) + DIM);
        v = *(const float4*)(src + c);
    } else if (r < NROW + PREV) {
        v = *(const float4*)(points + (size_t)(r - NROW) * DIM + c);
    }
    union { uint2 u; __nv_bfloat162 h[2]; } o;
    o.h[0] = __floats2bfloat162_rn(v.x, v.y);
    o.h[1] = __floats2bfloat162_rn(v.z, v.w);
    *(uint2*)(g_X + (size_t)r * DIM + c) = o.u;
}

// ---------------- symmetric GEMM, 128x256 tiles, 512 threads, 3-stage pipeline ----------------
#define ABUFA (128 * 64)              // A buffer elements (16KB)
#define ABUFB (256 * 64)              // B buffer elements (32KB)
#define BBASE (3 * ABUFA)
#define SMEM_SZ ((3 * ABUFA + 3 * ABUFB) * 2)   // 147456 bytes

__global__ __launch_bounds__(512, 1) void gemm_epi(const int* __restrict__ prevp)
{
    extern __shared__ __nv_bfloat16 sm[];   // [A0 A1 A2 | B0 B1 B2]

    const int PREV  = prevp ? *prevp : 100;
    const int NCOLS = NROW + PREV;

    // triangular map over (r: 128-row tile, c2: 256-col tile); include iff 2*c2+1 >= r
    int t = blockIdx.x, r = 0;
    for (;;) {
        int cap = 17 - (r >> 1);
        if (t < cap) break;
        t -= cap; ++r;
    }
    const int c2 = (r >> 1) + t;
    const int row0 = r * 128;
    const int col0 = c2 * 256;

    const int tid = threadIdx.x;
    const int lane = tid & 31, wid = tid >> 5;
    const int wr = wid >> 2, wc = wid & 3;       // 4x4 warp grid, warp tile 32x64

    float acc[2][8][4];
#pragma unroll
    for (int a = 0; a < 2; a++)
#pragma unroll
        for (int b = 0; b < 8; b++)
#pragma unroll
            for (int q = 0; q < 4; q++) acc[a][b][q] = 0.f;

    auto issue = [&](int it, int buf) {
        int k0 = it * 64;
#pragma unroll
        for (int h = 0; h < 2; ++h) {       // A: 128 rows
            int p = tid + h * 512;
            int rr = p >> 3, s = p & 7;
            const __nv_bfloat16* ga = g_X + (size_t)(row0 + rr) * DIM + k0 + s * 8;
            uint32_t sa = (uint32_t)__cvta_generic_to_shared(
                &sm[buf * ABUFA + rr * 64 + ((s ^ (rr & 7)) << 3)]);
            asm volatile("cp.async.cg.shared.global [%0], [%1], 16;" :: "r"(sa), "l"(ga));
        }
#pragma unroll
        for (int h = 0; h < 4; ++h) {       // B: 256 rows
            int p = tid + h * 512;
            int rr = p >> 3, s = p & 7;
            const __nv_bfloat16* gb = g_X + (size_t)(col0 + rr) * DIM + k0 + s * 8;
            uint32_t sb = (uint32_t)__cvta_generic_to_shared(
                &sm[BBASE + buf * ABUFB + rr * 64 + ((s ^ (rr & 7)) << 3)]);
            asm volatile("cp.async.cg.shared.global [%0], [%1], 16;" :: "r"(sb), "l"(gb));
        }
        asm volatile("cp.async.commit_group;");
    };

    issue(0, 0);
    issue(1, 1);

    int bufs = 0;          // rotates 0,1,2
#pragma unroll 1
    for (int it = 0; it < 16; ++it) {
        const int buf = bufs;
        bufs = (bufs == 2) ? 0 : bufs + 1;
        if (it < 15) asm volatile("cp.async.wait_group 1;");
        else         asm volatile("cp.async.wait_group 0;");
        __syncthreads();
        if (it + 2 < 16) {
            int nb = buf + 2; if (nb >= 3) nb -= 3;
            issue(it + 2, nb);
        }
#pragma unroll
        for (int kk = 0; kk < 4; ++kk) {
            uint32_t a[2][4];
#pragma unroll
            for (int mt = 0; mt < 2; ++mt) {
                int row = wr * 32 + mt * 16 + (lane & 15);
                int ch  = kk * 2 + (lane >> 4);
                uint32_t addr = (uint32_t)__cvta_generic_to_shared(
                    &sm[buf * ABUFA + row * 64 + ((ch ^ (row & 7)) << 3)]);
                asm volatile("ldmatrix.sync.aligned.m8n8.x4.shared.b16 {%0,%1,%2,%3}, [%4];"
                             : "=r"(a[mt][0]), "=r"(a[mt][1]), "=r"(a[mt][2]), "=r"(a[mt][3])
                             : "r"(addr));
            }
            uint32_t b[8][2];
#pragma unroll
            for (int nt2 = 0; nt2 < 4; ++nt2) {
                int row = wc * 64 + nt2 * 16 + (lane & 7) + ((lane & 16) >> 1);
                int ch  = kk * 2 + ((lane >> 3) & 1);
                uint32_t addr = (uint32_t)__cvta_generic_to_shared(
                    &sm[BBASE + buf * ABUFB + row * 64 + ((ch ^ (row & 7)) << 3)]);
                uint32_t r0, r1, r2, r3;
                asm volatile("ldmatrix.sync.aligned.m8n8.x4.shared.b16 {%0,%1,%2,%3}, [%4];"
                             : "=r"(r0), "=r"(r1), "=r"(r2), "=r"(r3) : "r"(addr));
                b[2 * nt2][0] = r0; b[2 * nt2][1] = r1;
                b[2 * nt2 + 1][0] = r2; b[2 * nt2 + 1][1] = r3;
            }
#pragma unroll
            for (int mt = 0; mt < 2; ++mt)
#pragma unroll
                for (int nt = 0; nt < 8; ++nt)
                    asm volatile("mma.sync.aligned.m16n8k16.row.col.f32.bf16.bf16.f32 "
                                 "{%0,%1,%2,%3},{%4,%5,%6,%7},{%8,%9},{%0,%1,%2,%3};"
                                 : "+f"(acc[mt][nt][0]), "+f"(acc[mt][nt][1]),
                                   "+f"(acc[mt][nt][2]), "+f"(acc[mt][nt][3])
                                 : "r"(a[mt][0]), "r"(a[mt][1]), "r"(a[mt][2]), "r"(a[mt][3]),
                                   "r"(b[nt][0]), "r"(b[nt][1]));
        }
    }

    // -------- epilogue: denominator only, per 128-col half of this warp --------
    const int csub = 2 * c2 + (wc >> 1);   // this warp's 128-col block index
    if (csub < r || csub >= 33) return;    // lower-triangle mirror or pure padding: skip
    const bool isdiag = (csub == r);
    const bool isprev = (csub == 32);
    const bool strict = (!isdiag && !isprev);

    float rowE[4] = {0.f, 0.f, 0.f, 0.f};
    float colE[16];
#pragma unroll
    for (int q = 0; q < 16; q++) colE[q] = 0.f;

    int irow[4];
#pragma unroll
    for (int rs = 0; rs < 4; rs++)
        irow[rs] = row0 + wr * 32 + (rs >> 1) * 16 + (rs & 1) * 8 + (lane >> 2);

#pragma unroll
    for (int mt = 0; mt < 2; ++mt)
#pragma unroll
        for (int nt = 0; nt < 8; ++nt)
#pragma unroll
            for (int q = 0; q < 4; ++q) {
                int rs = mt * 2 + (q >> 1);
                float e = ex2f(fmaf(acc[mt][nt][q], C1EXP, -C1EXP));
                if (!strict) {
                    int j = col0 + wc * 64 + nt * 8 + (lane & 3) * 2 + (q & 1);
                    if (isprev) { if (j >= NCOLS) e = 0.f; }
                    else        { if (j == irow[rs]) e = 0.f; }   // exact diag exclusion
                }
                rowE[rs] += e;
                colE[nt * 2 + (q & 1)] += e;
            }

#pragma unroll
    for (int rs = 0; rs < 4; rs++) {
        float v = rowE[rs];
        v += __shfl_xor_sync(0xffffffffu, v, 1);
        v += __shfl_xor_sync(0xffffffffu, v, 2);
        if ((lane & 3) == 0) atomicAdd(&g_acc[0][irow[rs]], v);
    }
    if (strict) {
#pragma unroll
        for (int idx = 0; idx < 16; ++idx) {
            float v = colE[idx];
            v += __shfl_xor_sync(0xffffffffu, v, 4);
            v += __shfl_xor_sync(0xffffffffu, v, 8);
            v += __shfl_xor_sync(0xffffffffu, v, 16);
            if (lane < 4) {
                int j = col0 + wc * 64 + (idx >> 1) * 8 + lane * 2 + (idx & 1);
                atomicAdd(&g_acc[0][j], v);
            }
        }
    }
}

// ---------------- positives (with inlined points_dot) + samix/slerp, warp per row ----------------
__global__ void pos_samix_k(const float* __restrict__ feats,
                            const float* __restrict__ sf, const float* __restrict__ points,
                            const float* __restrict__ lambp, const int* __restrict__ labels,
                            const int* __restrict__ mixed)
{
    int i = blockIdx.x * 8 + (threadIdx.x >> 5);
    int lane = threadIdx.x & 31;
    if (i >= NROW) return;
    int lab = g_lab[i];

    // ---- points_dot (fp32 exact) ----
    float xself;
    {
        const float* a = feats + ((i < BQ) ? (size_t)i * (2 * DIM)
                                           : (size_t)(i - BQ) * (2 * DIM) + DIM);
        const float* p = points + (size_t)lab * DIM;
        float s = 0.f;
        for (int k = lane * 4; k < DIM; k += 128) {
            float4 av = *(const float4*)(a + k);
            float4 pv = *(const float4*)(p + k);
            s += av.x * pv.x + av.y * pv.y + av.z * pv.z + av.w * pv.w;
        }
#pragma unroll
        for (int o = 16; o > 0; o >>= 1) s += __shfl_xor_sync(0xffffffffu, s, o);
        xself = s * TINV - TINV;
    }

    // ---- positives ----
    {
        int cnt = g_cnt[lab];
        if (cnt > BCAP) cnt = BCAP;

        const uint2* xi = (const uint2*)(g_X + (size_t)i * DIM);
        float rif[32];
#pragma unroll
        for (int k = 0; k < 8; ++k) {
            uint2 u = xi[lane + 32 * k];
            float2 f0 = __bfloat1622float2(*(const __nv_bfloat162*)&u.x);
            float2 f1 = __bfloat1622float2(*(const __nv_bfloat162*)&u.y);
            rif[k * 4 + 0] = f0.x; rif[k * 4 + 1] = f0.y;
            rif[k * 4 + 2] = f1.x; rif[k * 4 + 3] = f1.y;
        }

        float P0 = 0.f, P1 = 0.f, Pe = 0.f, Pex = 0.f, Pe2 = 0.f, Pe2x = 0.f;
        for (int b = 0; b < cnt; ++b) {
            int base = g_bucket[lab * BCAP + b];
#pragma unroll
            for (int v = 0; v < 2; ++v) {
                int j = base + v * BQ;
                float x;
                if (j == i) {
                    x = xself;
                } else {
                    const uint2* xj = (const uint2*)(g_X + (size_t)j * DIM);
                    float d = 0.f;
#pragma unroll
                    for (int k = 0; k < 8; ++k) {
                        uint2 u = xj[lane + 32 * k];
                        float2 f0 = __bfloat1622float2(*(const __nv_bfloat162*)&u.x);
                        float2 f1 = __bfloat1622float2(*(const __nv_bfloat162*)&u.y);
                        d = fmaf(rif[k * 4 + 0], f0.x, d);
                        d = fmaf(rif[k * 4 + 1], f0.y, d);
                        d = fmaf(rif[k * 4 + 2], f1.x, d);
                        d = fmaf(rif[k * 4 + 3], f1.y, d);
                    }
#pragma unroll
                    for (int o = 16; o > 0; o >>= 1) d += __shfl_xor_sync(0xffffffffu, d, o);
                    x = fmaf(d, TINV, -TINV);
                }
                float e = ex2f(x * LOG2E);
                P0 += 1.f; P1 += x; Pe += e;
                Pex += e * x; Pe2 += e * e; Pe2x += e * e * x;
            }
        }
        if (lane == 0) {
            g_acc[1][i] = P0; g_acc[2][i] = P1; g_acc[3][i] = Pe;
            g_acc[4][i] = Pex; g_acc[5][i] = Pe2; g_acc[6][i] = Pe2x;
        }
    }

    // ---- samix / slerp ----
    {
        int lr = labels[i & (BQ - 1)];
        int mi = mixed[i];
        int lp = labels[mi & (BQ - 1)];
        const float* corr = points + (size_t)lr * DIM;
        const float* perm = points + (size_t)lp * DIM;
        const float* s = sf + (size_t)i * DIM;
        float dcp = 0.f, dsc = 0.f, dsp = 0.f;
        for (int k = lane * 4; k < DIM; k += 128) {
            float4 cc = *(const float4*)(corr + k);
            float4 pp = *(const float4*)(perm + k);
            float4 vv = *(const float4*)(s + k);
            dcp += cc.x * pp.x + cc.y * pp.y + cc.z * pp.z + cc.w * pp.w;
            dsc += vv.x * cc.x + vv.y * cc.y + vv.z * cc.z + vv.w * cc.w;
            dsp += vv.x * pp.x + vv.y * pp.y + vv.z * pp.z + vv.w * pp.w;
        }
#pragma unroll
        for (int o = 16; o > 0; o >>= 1) {
            dcp += __shfl_xor_sync(0xffffffffu, dcp, o);
            dsc += __shfl_xor_sync(0xffffffffu, dsc, o);
            dsp += __shfl_xor_sync(0xffffffffu, dsp, o);
        }
        if (lane == 0) {
            float lamb = *lambp;
            float cost = fminf(1.f, fmaxf(-1.f, dcp));
            float theta = acosf(cost);
            float sval;
            if (theta < 1e-6f) {
                sval = dsc;
            } else {
                float st = sinf(theta);
                sval = (sinf(lamb * theta) / st) * dsc + (sinf((1.f - lamb) * theta) / st) * dsp;
            }
            float d = sval - 1.f;
            atomicAdd(&g_loss2, 0.5f * d * d);
        }
    }
}

// ---------------- finalize + combine (single block, fast log) + cleanup ----------------
__global__ void finalize_k(float* __restrict__ out)
{
    __shared__ float red[32];
    const int tid = threadIdx.x;
    const int lane = tid & 31, wid = tid >> 5;

    float val = 0.f;
    for (int i = tid; i < NROW; i += 1024) {
        float Dn = g_acc[0][i];
        float P0 = g_acc[1][i], P1 = g_acc[2][i], Pe = g_acc[3][i];
        float Pex = g_acc[4][i], Pe2 = g_acc[5][i], Pe2x = g_acc[6][i];
        float LD = lg2f(Dn) * LN2F;
        float inv = 1.f / Dn;
        float w0 = P0 - 2.f * Pe * inv + Pe2 * inv * inv;
        float wx = P1 - 2.f * Pex * inv + Pe2x * inv * inv;
        float S = wx - LD * w0;
        float pos = (P0 < 1e-6f) ? 1.f : P0;
        float mlpp = -S / pos;
        val += g_tmask[g_lab[i]] ? mlpp : 0.f;
        g_acc[0][i] = 0.f;                     // cleanup for next replay
    }
    __syncthreads();                           // all g_tmask reads done
    for (int i = tid; i < 1000; i += 1024) { g_cnt[i] = 0; g_tmask[i] = 0; }

#pragma unroll
    for (int o = 16; o > 0; o >>= 1) val += __shfl_xor_sync(0xffffffffu, val, o);
    if (lane == 0) red[wid] = val;
    __syncthreads();
    if (wid == 0) {
        float v = (lane < 32) ? red[lane] : 0.f;
#pragma unroll
        for (int o = 16; o > 0; o >>= 1) v += __shfl_xor_sync(0xffffffffu, v, o);
        if (lane == 0) {
            out[0] = (v + g_loss2) * (1.0f / (float)NROW);
            g_loss2 = 0.f;                     // cleanup for next replay
        }
    }
}

// ---------------- launch ----------------
extern "C" void kernel_launch(void* const* d_in, const int* in_sizes, int n_in,
                              void* d_out, int out_size)
{
    const float* features = (const float*)d_in[0];
    const float* samix    = (const float*)d_in[1];
    const float* points   = (const float*)d_in[2];
    const float* lamb     = (const float*)d_in[3];
    const int*   labels   = (const int*)d_in[4];
    const int*   tlab     = (const int*)d_in[5];
    const int*   mixed    = (const int*)d_in[6];
    const int*   prevp    = (n_in > 7) ? (const int*)d_in[7] : nullptr;
    int ntl = in_sizes[5];

    static bool attr_set = false;
    if (!attr_set) {
        cudaFuncSetAttribute(gemm_epi, cudaFuncAttributeMaxDynamicSharedMemorySize, SMEM_SZ);
        attr_set = true;
    }

    prep_all<<<(XPAD * DIM / 4 + 255) / 256, 256>>>(features, points, labels, tlab, ntl, prevp);
    gemm_epi<<<GTILES, 512, SMEM_SZ>>>(prevp);
    pos_samix_k<<<NROW / 8, 256>>>(features, samix, points, lamb, labels, mixed);
    finalize_k<<<1, 1024>>>((float*)d_out);
    (void)out_size;
}

// round 15
// speedup vs baseline: 1.3831x; 1.3831x over previous
#include <cuda_runtime.h>
#include <cuda_bf16.h>
#include <cstdint>

#define BQ    2048
#define DIM   1024
#define NROW  4096
#define XROWS 4224
#define NTILC 33
#define GTILES 560
#define TINV  14.285714285714285f
#define LOG2E 1.4426950408889634f
#define LN2F  0.6931471805599453f
#define C1EXP (TINV * LOG2E)
#define BCAP  64

// ---------------- scratch (device globals; zero-initialized, self-cleaning) ----------------
__device__ __nv_bfloat16 g_X[(size_t)XROWS * DIM];
__device__ int   g_lab[NROW];
__device__ float g_acc[7][NROW];      // [0]=E  [1..6]=P0,P1,Pe,Pex,Pe2,Pe2x
__device__ float g_loss2;             // samix sum + normal sum (both accumulate here)
__device__ unsigned int g_done;       // finalize last-block counter
__device__ int   g_cnt[1000];
__device__ int   g_bucket[1000 * BCAP];
__device__ unsigned char g_tmask[1000];

__device__ __forceinline__ float ex2f(float y)
{
    float r;
    asm("ex2.approx.ftz.f32 %0, %1;" : "=f"(r) : "f"(y));
    return r;
}
__device__ __forceinline__ float lg2f(float y)
{
    float r;
    asm("lg2.approx.ftz.f32 %0, %1;" : "=f"(r) : "f"(y));
    return r;
}

// ---------------- prep: X(bf16) + rep_labels + buckets + target mask ----------------
// 8 elements (2 independent float4 loads) per thread for MLP.
__global__ void prep_all(const float* __restrict__ feats,
                         const float* __restrict__ points,
                         const int* __restrict__ labels,
                         const int* __restrict__ tlab, int ntl,
                         const int* __restrict__ prevp)
{
    const int PREV = prevp ? *prevp : 100;
    int idx = blockIdx.x * blockDim.x + threadIdx.x;

    if (idx < NROW) g_lab[idx] = labels[idx & (BQ - 1)];
    if (idx < BQ) {
        int lab = labels[idx];
        int p = atomicAdd(&g_cnt[lab], 1);
        if (p < BCAP) g_bucket[lab * BCAP + p] = idx;
    }
    if (idx < ntl) g_tmask[tlab[idx]] = 1;

    int r = idx >> 7;
    int c = (idx & 127) << 3;
    if (r >= XROWS) return;
    float4 v0 = make_float4(0.f, 0.f, 0.f, 0.f);
    float4 v1 = v0;
    if (r < NROW) {
        const float* src = feats + ((r < BQ) ? (size_t)r * (2 * DIM)
                                             : (size_t)(r - BQ) * (2 * DIM) + DIM);
        v0 = *(const float4*)(src + c);
        v1 = *(const float4*)(src + c + 4);
    } else if (r < NROW + PREV) {
        const float* src = points + (size_t)(r - NROW) * DIM;
        v0 = *(const float4*)(src + c);
        v1 = *(const float4*)(src + c + 4);
    }
    union { uint4 u; __nv_bfloat162 h[4]; } o;
    o.h[0] = __floats2bfloat162_rn(v0.x, v0.y);
    o.h[1] = __floats2bfloat162_rn(v0.z, v0.w);
    o.h[2] = __floats2bfloat162_rn(v1.x, v1.y);
    o.h[3] = __floats2bfloat162_rn(v1.z, v1.w);
    *(uint4*)(g_X + (size_t)r * DIM + c) = o.u;
}

// ---------------- symmetric GEMM (mma.sync) + denominator epilogue (R6 proven config) ------
#define ABUF    (128 * 64)            // elements per buffer (16KB)
#define SMEM_SZ (6 * ABUF * 2)        // 98304 bytes

__global__ __launch_bounds__(256, 2) void gemm_epi(const int* __restrict__ prevp)
{
    extern __shared__ __nv_bfloat16 sm[];   // [A0 A1 A2 B0 B1 B2]

    const int PREV  = prevp ? *prevp : 100;
    const int NCOLS = NROW + PREV;

    int t = blockIdx.x, r = 0;
    while (t >= NTILC - r) { t -= NTILC - r; ++r; }
    const int c = r + t;
    const int row0 = r * 128;
    const int col0 = c * 128;
    const int tile_type = (c == NTILC - 1) ? 2 : (c == r ? 0 : 1);
    const bool diag = (tile_type == 0);
    const int bbase = diag ? 0 : 3 * ABUF;

    const int tid = threadIdx.x;
    const int lane = tid & 31, wid = tid >> 5;
    const int wr = wid >> 1, wc = wid & 1;

    float acc[2][8][4];
#pragma unroll
    for (int a = 0; a < 2; a++)
#pragma unroll
        for (int b = 0; b < 8; b++)
#pragma unroll
            for (int q = 0; q < 4; q++) acc[a][b][q] = 0.f;

    auto issue = [&](int it, int buf) {
        int k0 = it * 64;
#pragma unroll
        for (int h = 0; h < 4; ++h) {
            int p = tid + h * 256;
            int rr = p >> 3, s = p & 7;
            const __nv_bfloat16* ga = g_X + (size_t)(row0 + rr) * DIM + k0 + s * 8;
            uint32_t sa = (uint32_t)__cvta_generic_to_shared(
                &sm[buf * ABUF + rr * 64 + ((s ^ (rr & 7)) << 3)]);
            asm volatile("cp.async.cg.shared.global [%0], [%1], 16;" :: "r"(sa), "l"(ga));
        }
        if (!diag) {
#pragma unroll
            for (int h = 0; h < 4; ++h) {
                int p = tid + h * 256;
                int rr = p >> 3, s = p & 7;
                const __nv_bfloat16* gb = g_X + (size_t)(col0 + rr) * DIM + k0 + s * 8;
                uint32_t sb = (uint32_t)__cvta_generic_to_shared(
                    &sm[3 * ABUF + buf * ABUF + rr * 64 + ((s ^ (rr & 7)) << 3)]);
                asm volatile("cp.async.cg.shared.global [%0], [%1], 16;" :: "r"(sb), "l"(gb));
            }
        }
        asm volatile("cp.async.commit_group;");
    };

    issue(0, 0);
    issue(1, 1);

    int bufs = 0;          // rotates 0,1,2
#pragma unroll 1
    for (int it = 0; it < 16; ++it) {
        const int buf = bufs;
        bufs = (bufs == 2) ? 0 : bufs + 1;
        if (it < 15) asm volatile("cp.async.wait_group 1;");
        else         asm volatile("cp.async.wait_group 0;");
        __syncthreads();
        if (it + 2 < 16) {
            int nb = buf + 2; if (nb >= 3) nb -= 3;
            issue(it + 2, nb);
        }
#pragma unroll
        for (int kk = 0; kk < 4; ++kk) {
            uint32_t a[2][4];
#pragma unroll
            for (int mt = 0; mt < 2; ++mt) {
                int row = wr * 32 + mt * 16 + (lane & 15);
                int ch  = kk * 2 + (lane >> 4);
                uint32_t addr = (uint32_t)__cvta_generic_to_shared(
                    &sm[buf * ABUF + row * 64 + ((ch ^ (row & 7)) << 3)]);
                asm volatile("ldmatrix.sync.aligned.m8n8.x4.shared.b16 {%0,%1,%2,%3}, [%4];"
                             : "=r"(a[mt][0]), "=r"(a[mt][1]), "=r"(a[mt][2]), "=r"(a[mt][3])
                             : "r"(addr));
            }
            uint32_t b[8][2];
#pragma unroll
            for (int nt2 = 0; nt2 < 4; ++nt2) {
                int row = wc * 64 + nt2 * 16 + (lane & 7) + ((lane & 16) >> 1);
                int ch  = kk * 2 + ((lane >> 3) & 1);
                uint32_t addr = (uint32_t)__cvta_generic_to_shared(
                    &sm[bbase + buf * ABUF + row * 64 + ((ch ^ (row & 7)) << 3)]);
                uint32_t r0, r1, r2, r3;
                asm volatile("ldmatrix.sync.aligned.m8n8.x4.shared.b16 {%0,%1,%2,%3}, [%4];"
                             : "=r"(r0), "=r"(r1), "=r"(r2), "=r"(r3) : "r"(addr));
                b[2 * nt2][0] = r0; b[2 * nt2][1] = r1;
                b[2 * nt2 + 1][0] = r2; b[2 * nt2 + 1][1] = r3;
            }
#pragma unroll
            for (int mt = 0; mt < 2; ++mt)
#pragma unroll
                for (int nt = 0; nt < 8; ++nt)
                    asm volatile("mma.sync.aligned.m16n8k16.row.col.f32.bf16.bf16.f32 "
                                 "{%0,%1,%2,%3},{%4,%5,%6,%7},{%8,%9},{%0,%1,%2,%3};"
                                 : "+f"(acc[mt][nt][0]), "+f"(acc[mt][nt][1]),
                                   "+f"(acc[mt][nt][2]), "+f"(acc[mt][nt][3])
                                 : "r"(a[mt][0]), "r"(a[mt][1]), "r"(a[mt][2]), "r"(a[mt][3]),
                                   "r"(b[nt][0]), "r"(b[nt][1]));
        }
    }

    // -------- epilogue: denominator only --------
    float rowE[4] = {0.f, 0.f, 0.f, 0.f};
    float colE[16];
#pragma unroll
    for (int q = 0; q < 16; q++) colE[q] = 0.f;

    int irow[4];
#pragma unroll
    for (int rs = 0; rs < 4; rs++)
        irow[rs] = row0 + wr * 32 + (rs >> 1) * 16 + (rs & 1) * 8 + (lane >> 2);

#pragma unroll
    for (int mt = 0; mt < 2; ++mt)
#pragma unroll
        for (int nt = 0; nt < 8; ++nt)
#pragma unroll
            for (int q = 0; q < 4; ++q) {
                int rs = mt * 2 + (q >> 1);
                float e = ex2f(fmaf(acc[mt][nt][q], C1EXP, -C1EXP));
                if (tile_type != 1) {
                    int j = col0 + wc * 64 + nt * 8 + (lane & 3) * 2 + (q & 1);
                    if (tile_type == 2) { if (j >= NCOLS) e = 0.f; }
                    else                { if (j == irow[rs]) e = 0.f; }
                }
                rowE[rs] += e;
                colE[nt * 2 + (q & 1)] += e;
            }

#pragma unroll
    for (int rs = 0; rs < 4; rs++) {
        float v = rowE[rs];
        v += __shfl_xor_sync(0xffffffffu, v, 1);
        v += __shfl_xor_sync(0xffffffffu, v, 2);
        if ((lane & 3) == 0) atomicAdd(&g_acc[0][irow[rs]], v);
    }
    if (tile_type == 1) {
#pragma unroll
        for (int idx = 0; idx < 16; ++idx) {
            float v = colE[idx];
            v += __shfl_xor_sync(0xffffffffu, v, 4);
            v += __shfl_xor_sync(0xffffffffu, v, 8);
            v += __shfl_xor_sync(0xffffffffu, v, 16);
            if (lane < 4) {
                int j = col0 + wc * 64 + (idx >> 1) * 8 + lane * 2 + (idx & 1);
                atomicAdd(&g_acc[0][j], v);
            }
        }
    }
}

// ---------------- positives (with inlined points_dot) + samix/slerp, warp per row ----------------
__global__ void pos_samix_k(const float* __restrict__ feats,
                            const float* __restrict__ sf, const float* __restrict__ points,
                            const float* __restrict__ lambp, const int* __restrict__ labels,
                            const int* __restrict__ mixed)
{
    int i = blockIdx.x * 8 + (threadIdx.x >> 5);
    int lane = threadIdx.x & 31;
    if (i >= NROW) return;
    int lab = g_lab[i];

    // ---- points_dot (fp32 exact) ----
    float xself;
    {
        const float* a = feats + ((i < BQ) ? (size_t)i * (2 * DIM)
                                           : (size_t)(i - BQ) * (2 * DIM) + DIM);
        const float* p = points + (size_t)lab * DIM;
        float s = 0.f;
        for (int k = lane * 4; k < DIM; k += 128) {
            float4 av = *(const float4*)(a + k);
            float4 pv = *(const float4*)(p + k);
            s += av.x * pv.x + av.y * pv.y + av.z * pv.z + av.w * pv.w;
        }
#pragma unroll
        for (int o = 16; o > 0; o >>= 1) s += __shfl_xor_sync(0xffffffffu, s, o);
        xself = s * TINV - TINV;
    }

    // ---- positives ----
    {
        int cnt = g_cnt[lab];
        if (cnt > BCAP) cnt = BCAP;

        const uint2* xi = (const uint2*)(g_X + (size_t)i * DIM);
        float rif[32];
#pragma unroll
        for (int k = 0; k < 8; ++k) {
            uint2 u = xi[lane + 32 * k];
            float2 f0 = __bfloat1622float2(*(const __nv_bfloat162*)&u.x);
            float2 f1 = __bfloat1622float2(*(const __nv_bfloat162*)&u.y);
            rif[k * 4 + 0] = f0.x; rif[k * 4 + 1] = f0.y;
            rif[k * 4 + 2] = f1.x; rif[k * 4 + 3] = f1.y;
        }

        float P0 = 0.f, P1 = 0.f, Pe = 0.f, Pex = 0.f, Pe2 = 0.f, Pe2x = 0.f;
        for (int b = 0; b < cnt; ++b) {
            int base = g_bucket[lab * BCAP + b];
#pragma unroll
            for (int v = 0; v < 2; ++v) {
                int j = base + v * BQ;
                float x;
                if (j == i) {
                    x = xself;
                } else {
                    const uint2* xj = (const uint2*)(g_X + (size_t)j * DIM);
                    float d = 0.f;
#pragma unroll
                    for (int k = 0; k < 8; ++k) {
                        uint2 u = xj[lane + 32 * k];
                        float2 f0 = __bfloat1622float2(*(const __nv_bfloat162*)&u.x);
                        float2 f1 = __bfloat1622float2(*(const __nv_bfloat162*)&u.y);
                        d = fmaf(rif[k * 4 + 0], f0.x, d);
                        d = fmaf(rif[k * 4 + 1], f0.y, d);
                        d = fmaf(rif[k * 4 + 2], f1.x, d);
                        d = fmaf(rif[k * 4 + 3], f1.y, d);
                    }
#pragma unroll
                    for (int o = 16; o > 0; o >>= 1) d += __shfl_xor_sync(0xffffffffu, d, o);
                    x = fmaf(d, TINV, -TINV);
                }
                float e = ex2f(x * LOG2E);
                P0 += 1.f; P1 += x; Pe += e;
                Pex += e * x; Pe2 += e * e; Pe2x += e * e * x;
            }
        }
        if (lane == 0) {
            g_acc[1][i] = P0; g_acc[2][i] = P1; g_acc[3][i] = Pe;
            g_acc[4][i] = Pex; g_acc[5][i] = Pe2; g_acc[6][i] = Pe2x;
        }
    }

    // ---- samix / slerp ----
    {
        int lr = labels[i & (BQ - 1)];
        int mi = mixed[i];
        int lp = labels[mi & (BQ - 1)];
        const float* corr = points + (size_t)lr * DIM;
        const float* perm = points + (size_t)lp * DIM;
        const float* s = sf + (size_t)i * DIM;
        float dcp = 0.f, dsc = 0.f, dsp = 0.f;
        for (int k = lane * 4; k < DIM; k += 128) {
            float4 cc = *(const float4*)(corr + k);
            float4 pp = *(const float4*)(perm + k);
            float4 vv = *(const float4*)(s + k);
            dcp += cc.x * pp.x + cc.y * pp.y + cc.z * pp.z + cc.w * pp.w;
            dsc += vv.x * cc.x + vv.y * cc.y + vv.z * cc.z + vv.w * cc.w;
            dsp += vv.x * pp.x + vv.y * pp.y + vv.z * pp.z + vv.w * pp.w;
        }
#pragma unroll
        for (int o = 16; o > 0; o >>= 1) {
            dcp += __shfl_xor_sync(0xffffffffu, dcp, o);
            dsc += __shfl_xor_sync(0xffffffffu, dsc, o);
            dsp += __shfl_xor_sync(0xffffffffu, dsp, o);
        }
        if (lane == 0) {
            float lamb = *lambp;
            float cost = fminf(1.f, fmaxf(-1.f, dcp));
            float theta = acosf(cost);
            float sval;
            if (theta < 1e-6f) {
                sval = dsc;
            } else {
                float st = sinf(theta);
                sval = (sinf(lamb * theta) / st) * dsc + (sinf((1.f - lamb) * theta) / st) * dsp;
            }
            float d = sval - 1.f;
            atomicAdd(&g_loss2, 0.5f * d * d);
        }
    }
}

// ---------------- finalize: 16 blocks; last block writes output + cleans up ----------------
__global__ void finalize_k(float* __restrict__ out)
{
    __shared__ float red[8];
    __shared__ int slast;
    const int tid = threadIdx.x;
    const int lane = tid & 31, wid = tid >> 5;
    const int i = blockIdx.x * 256 + tid;

    float Dn = g_acc[0][i];
    float P0 = g_acc[1][i], P1 = g_acc[2][i], Pe = g_acc[3][i];
    float Pex = g_acc[4][i], Pe2 = g_acc[5][i], Pe2x = g_acc[6][i];
    float LD = lg2f(Dn) * LN2F;
    float inv = 1.f / Dn;
    float w0 = P0 - 2.f * Pe * inv + Pe2 * inv * inv;
    float wx = P1 - 2.f * Pex * inv + Pe2x * inv * inv;
    float S = wx - LD * w0;
    float pos = (P0 < 1e-6f) ? 1.f : P0;
    float mlpp = -S / pos;
    float val = g_tmask[g_lab[i]] ? mlpp : 0.f;
    g_acc[0][i] = 0.f;                         // cleanup own slice (already read)

#pragma unroll
    for (int o = 16; o > 0; o >>= 1) val += __shfl_xor_sync(0xffffffffu, val, o);
    if (lane == 0) red[wid] = val;
    __syncthreads();
    if (tid == 0) {
        float v = red[0] + red[1] + red[2] + red[3] + red[4] + red[5] + red[6] + red[7];
        atomicAdd(&g_loss2, v);
        __threadfence();
        unsigned int done = atomicAdd(&g_done, 1u);
        slast = (done == gridDim.x - 1) ? 1 : 0;
    }
    __syncthreads();
    if (slast) {
        for (int k = tid; k < 1000; k += 256) { g_cnt[k] = 0; g_tmask[k] = 0; }
        if (tid == 0) {
            out[0] = g_loss2 * (1.0f / (float)NROW);
            g_loss2 = 0.f;                     // cleanup for next replay
            g_done = 0u;
        }
    }
}

// ---------------- launch ----------------
extern "C" void kernel_launch(void* const* d_in, const int* in_sizes, int n_in,
                              void* d_out, int out_size)
{
    const float* features = (const float*)d_in[0];
    const float* samix    = (const float*)d_in[1];
    const float* points   = (const float*)d_in[2];
    const float* lamb     = (const float*)d_in[3];
    const int*   labels   = (const int*)d_in[4];
    const int*   tlab     = (const int*)d_in[5];
    const int*   mixed    = (const int*)d_in[6];
    const int*   prevp    = (n_in > 7) ? (const int*)d_in[7] : nullptr;
    int ntl = in_sizes[5];

    static bool attr_set = false;
    if (!attr_set) {
        cudaFuncSetAttribute(gemm_epi, cudaFuncAttributeMaxDynamicSharedMemorySize, SMEM_SZ);
        attr_set = true;
    }

    prep_all<<<(XROWS * DIM / 8 + 255) / 256, 256>>>(features, points, labels, tlab, ntl, prevp);
    gemm_epi<<<GTILES, 256, SMEM_SZ>>>(prevp);
    pos_samix_k<<<NROW / 8, 256>>>(features, samix, points, lamb, labels, mixed);
    finalize_k<<<NROW / 256, 256>>>((float*)d_out);
    (void)out_size;
}